// round 14
// baseline (speedup 1.0000x reference)
#include <cuda_runtime.h>

#define NN 204800
#define EE 1638400
#define BB 4096
#define KTOP 10
#define NPG 50

// ---------------- scratch (no allocation allowed) ----------------
__device__ float g_dinv[NN];
__device__ int   g_cnt[NN];
__device__ int   g_off[NN];      // within-1024-chunk exclusive offsets
__device__ int   g_cur[NN];
__device__ int   g_bsum[200];    // RAW per-chunk totals (consumers scan locally)
__device__ int2  g_edge[EE];                 // {src, coef bits}
__device__ float g_h[(size_t)NN * 64];       // GEMM output per layer
__device__ float g_feat[(size_t)NN * 192];   // x1 | x2 | x3 concat
__device__ float g_key[NN];                  // per-node max feature

// ---------------- degree count (4 edges / thread) ----------------
__global__ void k_count(const int4* __restrict__ col4) {
    int e = blockIdx.x * 256 + threadIdx.x;
    int4 c = col4[e];
    atomicAdd(&g_cnt[c.x], 1);
    atomicAdd(&g_cnt[c.y], 1);
    atomicAdd(&g_cnt[c.z], 1);
    atomicAdd(&g_cnt[c.w], 1);
}

__global__ void k_scan_blk() {
    __shared__ int sh[1024];
    int t = threadIdx.x, i = blockIdx.x * 1024 + t;
    int v = g_cnt[i];
    g_dinv[i] = rsqrtf((float)v + 1.0f);   // fused: dinv from raw degree
    g_cur[i] = 0;                          // fused: scatter cursor init
    sh[t] = v; __syncthreads();
    for (int d = 1; d < 1024; d <<= 1) {
        int a = (t >= d) ? sh[t - d] : 0; __syncthreads();
        sh[t] += a; __syncthreads();
    }
    g_off[i] = sh[t] - v;                 // exclusive within chunk
    if (t == 1023) g_bsum[blockIdx.x] = sh[1023];   // raw chunk total
}

// local exclusive scan of the 200 chunk totals into smem (any 256-thr block)
__device__ __forceinline__ void scan_bases(int* sbs, int t) {
    int v = (t < 200) ? g_bsum[t] : 0;
    sbs[t] = v; __syncthreads();
    for (int d = 1; d < 256; d <<= 1) {
        int a = (t >= d) ? sbs[t - d] : 0; __syncthreads();
        sbs[t] += a; __syncthreads();
    }
    int ex = sbs[t] - v;
    __syncthreads();
    sbs[t] = ex;
    __syncthreads();
}

// ---------------- packed f32x2 FMA ----------------
__device__ __forceinline__ float2 ffma2(float2 a, float2 b, float2 c) {
    float2 d;
    asm("fma.rn.f32x2 %0, %1, %2, %3;"
        : "=l"(*(unsigned long long*)&d)
        : "l"(*(unsigned long long*)&a),
          "l"(*(unsigned long long*)&b),
          "l"(*(unsigned long long*)&c));
    return d;
}

// ---------------- GEMM core: 64 rows x 64 cols per block, 8 rows/warp -------
// low register footprint (acc = 16 regs) -> 5+ blocks/SM
template<int KDIM>
__device__ __forceinline__ void gemm_body(float* Ws, float* xs,
                                          const float* __restrict__ xrow,
                                          const float* __restrict__ W,
                                          int row0, int t) {
    int w = t >> 5, lane = t & 31;
    for (int i = t; i < KDIM * 64; i += 256) Ws[i] = W[i];
    int r = w * 8;                         // warp's first row in tile
    int rr = t & 63;                       // staging row
    int kq = t >> 6;                       // staging float4-col (0..3)
    float2 acc[4][2];
#pragma unroll
    for (int i = 0; i < 4; i++) { acc[i][0] = make_float2(0.f, 0.f); acc[i][1] = acc[i][0]; }
    for (int kb = 0; kb < KDIM; kb += 16) {
        __syncthreads();
        {
            float4 v = *(const float4*)&xrow[kb + kq * 4];
            xs[(kq * 4 + 0) * 64 + rr] = v.x;
            xs[(kq * 4 + 1) * 64 + rr] = v.y;
            xs[(kq * 4 + 2) * 64 + rr] = v.z;
            xs[(kq * 4 + 3) * 64 + rr] = v.w;
        }
        __syncthreads();
#pragma unroll
        for (int k = 0; k < 16; k++) {
            float2 wv = *(const float2*)&Ws[(kb + k) * 64 + lane * 2];
            float2 W0 = make_float2(wv.x, wv.x);
            float2 W1 = make_float2(wv.y, wv.y);
            const float4* xp = (const float4*)&xs[k * 64 + r];
            float4 xa = xp[0], xb = xp[1];
            float2 p;
            p = make_float2(xa.x, xa.y);
            acc[0][0] = ffma2(p, W0, acc[0][0]); acc[0][1] = ffma2(p, W1, acc[0][1]);
            p = make_float2(xa.z, xa.w);
            acc[1][0] = ffma2(p, W0, acc[1][0]); acc[1][1] = ffma2(p, W1, acc[1][1]);
            p = make_float2(xb.x, xb.y);
            acc[2][0] = ffma2(p, W0, acc[2][0]); acc[2][1] = ffma2(p, W1, acc[2][1]);
            p = make_float2(xb.z, xb.w);
            acc[3][0] = ffma2(p, W0, acc[3][0]); acc[3][1] = ffma2(p, W1, acc[3][1]);
        }
    }
#pragma unroll
    for (int i = 0; i < 4; i++) {
        size_t rb = (size_t)(row0 + r + 2 * i) * 64 + lane * 2;
        *(float2*)&g_h[rb]      = make_float2(acc[i][0].x, acc[i][1].x);
        *(float2*)&g_h[rb + 64] = make_float2(acc[i][0].y, acc[i][1].y);
    }
}

// ---------------- fused: GEMM1 (blocks < 3200) + CSR scatter (>= 3200) ------
__global__ __launch_bounds__(256, 5)
void k_build(const int4* __restrict__ row4, const int4* __restrict__ col4,
             const float* __restrict__ x, const float* __restrict__ W) {
    __shared__ float sm[128 * 64 + 16 * 64];   // Ws | xs (gemm) ; scan (scatter)
    int b = blockIdx.x;
    int t = threadIdx.x;
    if (b < 3200) {
        int row0 = b * 64;
        const float* xrow = x + (size_t)(row0 + (t & 63)) * 128;
        gemm_body<128>(sm, sm + 128 * 64, xrow, W, row0, t);
    } else {
        // ---- scatter role: local scan of chunk bases, then 4 edges/thread --
        int* sbs = (int*)sm;
        scan_bases(sbs, t);
        int e = (b - 3200) * 256 + t;
        int4 r4 = row4[e], c4 = col4[e];
        int cs[4] = {c4.x, c4.y, c4.z, c4.w};
        int rs[4] = {r4.x, r4.y, r4.z, r4.w};
#pragma unroll
        for (int j = 0; j < 4; j++) {
            int c = cs[j], r = rs[j];
            int pos = g_off[c] + sbs[c >> 10] + atomicAdd(&g_cur[c], 1);
            g_edge[pos] = make_int2(r, __float_as_int(g_dinv[r] * g_dinv[c]));
        }
    }
}

// ---------------- GEMM layers 2,3: h = feat_slice @ W ----------------
__global__ __launch_bounds__(256, 5)
void k_gemm64(int inoff, const float* __restrict__ W) {
    __shared__ float sm[64 * 64 + 16 * 64];
    int t = threadIdx.x;
    int row0 = blockIdx.x * 64;
    const float* xrow = (const float*)g_feat + (size_t)(row0 + (t & 63)) * 192 + inoff;
    gemm_body<64>(sm, sm + 64 * 64, xrow, W, row0, t);
}

// ---------------- aggregation: one warp per target node -------------------
// half-warp edge split: 4x LDG.128 per 8 edges (2 edges per load), f32x2 FMA.
// fused: per-node sort-key running max. Chunk bases scanned locally in smem.
__global__ void k_agg(const float* __restrict__ bias, int outoff, int first) {
    __shared__ int sbs[256];
    scan_bases(sbs, threadIdx.x);
    int n = (blockIdx.x * 256 + threadIdx.x) >> 5;
    int lane = threadIdx.x & 31;
    int half = lane >> 4;           // 0: even edges, 1: odd edges
    int c4 = (lane & 15) * 4;       // 4 cols per lane (16 lanes cover 64 cols)
    float di = g_dinv[n];
    float ssel = half ? 0.f : di * di;
    float4 hv = *(const float4*)&g_h[(size_t)n * 64 + c4];
    float2 acc0 = make_float2(hv.x * ssel, hv.y * ssel);
    float2 acc1 = make_float2(hv.z * ssel, hv.w * ssel);
    int beg = g_off[n] + sbs[n >> 10], deg = g_cnt[n];
    for (int bb = 0; bb < deg; bb += 32) {
        int rem = deg - bb;
        int cnt = rem < 32 ? rem : 32;
        int2 ed = (lane < cnt) ? g_edge[beg + bb + lane] : make_int2(n, 0);
        int se = ed.x;
        float ce = __int_as_float(ed.y);
        for (int i = 0; i < cnt; i += 8) {
            int sj[4]; float cj[4];
#pragma unroll
            for (int j = 0; j < 4; j++) {
                int idx = i + j * 2 + half;
                sj[j] = __shfl_sync(0xffffffffu, se, idx & 31);
                float c = __shfl_sync(0xffffffffu, ce, idx & 31);
                cj[j] = (idx < cnt) ? c : 0.f;
            }
            float4 v[4];
#pragma unroll
            for (int j = 0; j < 4; j++)
                v[j] = *(const float4*)&g_h[(size_t)sj[j] * 64 + c4];
#pragma unroll
            for (int j = 0; j < 4; j++) {
                float2 cc = make_float2(cj[j], cj[j]);
                acc0 = ffma2(make_float2(v[j].x, v[j].y), cc, acc0);
                acc1 = ffma2(make_float2(v[j].z, v[j].w), cc, acc1);
            }
        }
    }
    // combine the two edge-halves
    acc0.x += __shfl_xor_sync(0xffffffffu, acc0.x, 16);
    acc0.y += __shfl_xor_sync(0xffffffffu, acc0.y, 16);
    acc1.x += __shfl_xor_sync(0xffffffffu, acc1.x, 16);
    acc1.y += __shfl_xor_sync(0xffffffffu, acc1.y, 16);
    float m = -3.4e38f;
    if (half == 0) {
        float4 bv = *(const float4*)&bias[c4];
        float t0 = tanhf(acc0.x + bv.x);
        float t1 = tanhf(acc0.y + bv.y);
        float t2 = tanhf(acc1.x + bv.z);
        float t3 = tanhf(acc1.y + bv.w);
        *(float4*)&g_feat[(size_t)n * 192 + outoff + c4] = make_float4(t0, t1, t2, t3);
        m = fmaxf(fmaxf(t0, t1), fmaxf(t2, t3));
    }
#pragma unroll
    for (int d = 16; d > 0; d >>= 1) m = fmaxf(m, __shfl_xor_sync(0xffffffffu, m, d));
    if (lane == 0) g_key[n] = first ? m : fmaxf(g_key[n], m);
}

// ---------------- fused head: select + sort + conv1/pool/conv2/pool + FC ----
__global__ __launch_bounds__(320, 6)
void k_cnn(const float* __restrict__ Wc1, const float* __restrict__ bc1,
           const float* __restrict__ Wc2, const float* __restrict__ bc2,
           const float* __restrict__ Wf,  const float* __restrict__ bf,
           float* __restrict__ out_c, float* __restrict__ out_xf) {
    __shared__ float sp[10 * 192];   // sorted pooled tile (channel-major)
    __shared__ float s1[32 * 48];
    __shared__ float s2[32 * 12];
    __shared__ float s3[64 * 4];
    __shared__ float sxf[64];
    __shared__ float sk[64];
    __shared__ int   sel[16];
    int g = blockIdx.x, t = threadIdx.x;
    int w = t >> 5, lane = t & 31;

    if (t < NPG) {
        sk[t] = g_key[g * NPG + t];
        g_cnt[g * NPG + t] = 0;          // reset degree counters for next replay
    }
    __syncthreads();

    if (t < NPG) {
        float kv = sk[t];
        int r = 0;
        for (int j = 0; j < NPG; j++) {
            float kj = sk[j];
            r += (int)((kj > kv) || ((kj == kv) && (j < t)));
        }
        if (r < KTOP) sel[r] = g * NPG + t;
    }
    __syncthreads();

    // warps 0..9: sort own selected node's 192 feats ascending (bitonic-256)
    if (w < KTOP) {
        int node = sel[w];
        const float* f = g_feat + (size_t)node * 192;
        const float INF = __int_as_float(0x7f800000);
        float v[8];
#pragma unroll
        for (int r = 0; r < 8; r++) {
            int idx = r * 32 + lane;
            v[r] = (idx < 192) ? f[idx] : INF;
        }
#pragma unroll
        for (int k = 2; k <= 256; k <<= 1) {
#pragma unroll
            for (int j = 128; j > 0; j >>= 1) {
                if (j >= k) continue;
                if (j < 32) {
#pragma unroll
                    for (int r = 0; r < 8; r++) {
                        int idx = r * 32 + lane;
                        float o = __shfl_xor_sync(0xffffffffu, v[r], j);
                        bool up = ((idx & k) == 0);
                        bool lower = ((lane & j) == 0);
                        v[r] = (up == lower) ? fminf(v[r], o) : fmaxf(v[r], o);
                    }
                } else {
                    int jr = j >> 5;
#pragma unroll
                    for (int r = 0; r < 8; r++) {
                        if ((r & jr) == 0) {
                            int r2 = r | jr;
                            int idx = r * 32 + lane;
                            bool up = ((idx & k) == 0);
                            float a = v[r], b = v[r2];
                            v[r]  = up ? fminf(a, b) : fmaxf(a, b);
                            v[r2] = up ? fmaxf(a, b) : fminf(a, b);
                        }
                    }
                }
            }
        }
#pragma unroll
        for (int r = 0; r < 6; r++) sp[w * 192 + r * 32 + lane] = v[r];
    }
    __syncthreads();

    // conv1 (C_in=10, k=4, stride=4) + relu -> s1[32][48]
    if (w < 8) {
        const float4* sp4 = (const float4*)sp;
#pragma unroll
        for (int oo = 0; oo < 4; oo++) {
            int o = w * 4 + oo;
            const float4* w4 = (const float4*)&Wc1[o * 40];
            float a0 = bc1[o], a1 = a0;
#pragma unroll
            for (int i = 0; i < 10; i++) {
                float4 wv = w4[i];
                float4 xa = sp4[i * 48 + lane];
                a0 = fmaf(xa.x, wv.x, a0); a0 = fmaf(xa.y, wv.y, a0);
                a0 = fmaf(xa.z, wv.z, a0); a0 = fmaf(xa.w, wv.w, a0);
                if (lane < 16) {
                    float4 xb = sp4[i * 48 + 32 + lane];
                    a1 = fmaf(xb.x, wv.x, a1); a1 = fmaf(xb.y, wv.y, a1);
                    a1 = fmaf(xb.z, wv.z, a1); a1 = fmaf(xb.w, wv.w, a1);
                }
            }
            s1[o * 48 + lane] = fmaxf(a0, 0.f);
            if (lane < 16) s1[o * 48 + 32 + lane] = fmaxf(a1, 0.f);
        }
    }
    __syncthreads();

    // maxpool 4/4 -> s2[32][12]
    for (int idx = t; idx < 384; idx += 320) {
        int o = idx / 12, p = idx % 12;
        const float* r0 = &s1[o * 48 + p * 4];
        s2[idx] = fmaxf(fmaxf(r0[0], r0[1]), fmaxf(r0[2], r0[3]));
    }
    __syncthreads();

    // conv2 (C_in=32, k=3, stride=3) + relu -> s3[64][4]
    if (w < 8) {
        int p = lane & 3, ipart = lane >> 2;
#pragma unroll
        for (int j = 0; j < 8; j++) {
            int o = w * 8 + j;
            float acc = 0.f;
#pragma unroll
            for (int m = 0; m < 4; m++) {
                int i = ipart + m * 8;
                const float* s2r = &s2[i * 12 + p * 3];
                const float* w2r = &Wc2[o * 96 + i * 3];
                acc = fmaf(s2r[0], w2r[0], acc);
                acc = fmaf(s2r[1], w2r[1], acc);
                acc = fmaf(s2r[2], w2r[2], acc);
            }
            acc += __shfl_xor_sync(0xffffffffu, acc, 4);
            acc += __shfl_xor_sync(0xffffffffu, acc, 8);
            acc += __shfl_xor_sync(0xffffffffu, acc, 16);
            if (lane < 4) s3[o * 4 + p] = fmaxf(acc + bc2[o], 0.f);
        }
    }
    __syncthreads();

    // maxpool 4 -> xf[64]
    if (t < 64) {
        float m = fmaxf(fmaxf(s3[t * 4], s3[t * 4 + 1]),
                        fmaxf(s3[t * 4 + 2], s3[t * 4 + 3]));
        sxf[t] = m;
        out_xf[(size_t)g * 64 + t] = m;
    }
    __syncthreads();

    // FC: c = relu(xf) @ Wf + bf
    if (t < 10) {
        float acc = bf[t];
#pragma unroll
        for (int o = 0; o < 64; o++)
            acc = fmaf(fmaxf(sxf[o], 0.f), Wf[o * 10 + t], acc);
        out_c[(size_t)g * 10 + t] = acc;
    }
}

// ---------------- launcher ----------------
extern "C" void kernel_launch(void* const* d_in, const int* in_sizes, int n_in,
                              void* d_out, int out_size) {
    const float* x   = (const float*)d_in[0];
    const int*   ei  = (const int*)d_in[1];
    // d_in[2] = batch (implicit: repeat(arange(B), 50))
    const float* W1  = (const float*)d_in[3];
    const float* b1  = (const float*)d_in[4];
    const float* W2  = (const float*)d_in[5];
    const float* b2  = (const float*)d_in[6];
    const float* W3  = (const float*)d_in[7];
    const float* b3  = (const float*)d_in[8];
    const float* Wc1 = (const float*)d_in[9];
    const float* bc1 = (const float*)d_in[10];
    const float* Wc2 = (const float*)d_in[11];
    const float* bc2 = (const float*)d_in[12];
    const float* Wf  = (const float*)d_in[13];
    const float* bf  = (const float*)d_in[14];
    float* out = (float*)d_out;
    float* out_c  = out;                   // [B,10]
    float* out_xf = out + (size_t)BB * 10; // [B,64]

    const int4* row4 = (const int4*)ei;
    const int4* col4 = (const int4*)(ei + EE);

    // degree + CSR build (g_cnt zeroed by previous call's k_cnn; statics start 0)
    k_count<<<EE / 1024, 256>>>(col4);                 // launch 1
    k_scan_blk<<<200, 1024>>>();                       // launch 2 (+dinv +cursor)
    // fused: GEMM layer 1 (blocks 0..3199) + edge scatter (3200..4799)
    k_build<<<4800, 256>>>(row4, col4, x, W1);         // launch 3
    k_agg<<<NN * 32 / 256, 256>>>(b1, 0, 1);           // launch 4 <- ncu slot
    // layer 2
    k_gemm64<<<NN / 64, 256>>>(0, W2);
    k_agg<<<NN * 32 / 256, 256>>>(b2, 64, 0);
    // layer 3
    k_gemm64<<<NN / 64, 256>>>(64, W3);
    k_agg<<<NN * 32 / 256, 256>>>(b3, 128, 0);

    // fused select + sort + CNN head + FC (also resets g_cnt for next replay)
    k_cnn<<<BB, 320>>>(Wc1, bc1, Wc2, bc2, Wf, bf, out_c, out_xf);
}

// round 15
// speedup vs baseline: 1.2198x; 1.2198x over previous
#include <cuda_runtime.h>

#define NN 204800
#define EE 1638400
#define BB 4096
#define KTOP 10
#define NPG 50

// ---------------- scratch (no allocation allowed) ----------------
__device__ float g_dinv[NN];
__device__ int   g_cnt[NN];
__device__ int   g_off[NN];      // within-1024-chunk exclusive offsets
__device__ int   g_cur[NN];
__device__ int   g_bsum[200];    // chunk totals -> exclusive-scanned in place
__device__ int2  g_edge[EE];                 // {src, coef bits}
__device__ float g_h[(size_t)NN * 64];       // GEMM output per layer
__device__ float g_feat[(size_t)NN * 192];   // x1 | x2 | x3 concat
__device__ float g_key[NN];                  // per-node max feature

// ---------------- degree count (4 edges / thread) ----------------
__global__ void k_count(const int4* __restrict__ col4) {
    int e = blockIdx.x * 256 + threadIdx.x;
    int4 c = col4[e];
    atomicAdd(&g_cnt[c.x], 1);
    atomicAdd(&g_cnt[c.y], 1);
    atomicAdd(&g_cnt[c.z], 1);
    atomicAdd(&g_cnt[c.w], 1);
}

__global__ void k_scan_blk() {
    __shared__ int sh[1024];
    int t = threadIdx.x, i = blockIdx.x * 1024 + t;
    int v = g_cnt[i];
    g_dinv[i] = rsqrtf((float)v + 1.0f);   // fused: dinv from raw degree
    g_cur[i] = 0;                          // fused: scatter cursor init
    sh[t] = v; __syncthreads();
    for (int d = 1; d < 1024; d <<= 1) {
        int a = (t >= d) ? sh[t - d] : 0; __syncthreads();
        sh[t] += a; __syncthreads();
    }
    g_off[i] = sh[t] - v;                 // exclusive within chunk
    if (t == 1023) g_bsum[blockIdx.x] = sh[1023];
}

// in-place exclusive scan of the 200 chunk totals (single block, ~4us)
__global__ void k_scan_top() {
    __shared__ int sh[256];
    int t = threadIdx.x;
    int v = (t < 200) ? g_bsum[t] : 0;
    sh[t] = v; __syncthreads();
    for (int d = 1; d < 256; d <<= 1) {
        int a = (t >= d) ? sh[t - d] : 0; __syncthreads();
        sh[t] += a; __syncthreads();
    }
    if (t < 200) g_bsum[t] = sh[t] - v;   // exclusive
}

// ---------------- scatter: 4 edges / thread ----------------
__global__ void k_scatter(const int4* __restrict__ row4, const int4* __restrict__ col4) {
    int e = blockIdx.x * 256 + threadIdx.x;
    int4 r4 = row4[e], c4 = col4[e];
    int cs[4] = {c4.x, c4.y, c4.z, c4.w};
    int rs[4] = {r4.x, r4.y, r4.z, r4.w};
#pragma unroll
    for (int j = 0; j < 4; j++) {
        int c = cs[j], r = rs[j];
        int pos = g_off[c] + g_bsum[c >> 10] + atomicAdd(&g_cur[c], 1);
        g_edge[pos] = make_int2(r, __float_as_int(g_dinv[r] * g_dinv[c]));
    }
}

// ---------------- packed f32x2 FMA ----------------
__device__ __forceinline__ float2 ffma2(float2 a, float2 b, float2 c) {
    float2 d;
    asm("fma.rn.f32x2 %0, %1, %2, %3;"
        : "=l"(*(unsigned long long*)&d)
        : "l"(*(unsigned long long*)&a),
          "l"(*(unsigned long long*)&b),
          "l"(*(unsigned long long*)&c));
    return d;
}

// exact-formula tanh via MUFU: 1 - 2/(e^{2x}+1). ~5 ops, abs err ~1e-6.
__device__ __forceinline__ float fast_tanh(float x) {
    float e = exp2f(2.885390081777927f * x);   // e^{2x}
    return 1.0f - __fdividef(2.0f, e + 1.0f);
}

// ---------------- GEMM: h = in @ W  (proven 128-row / 16-rows-per-warp) -----
template<int KDIM>
__global__ void k_gemm(const float* __restrict__ xin, int instride, int inoff,
                       const float* __restrict__ W) {
    __shared__ float Ws[KDIM * 64];
    __shared__ float xs[16 * 128];
    int t = threadIdx.x;
    int w = t >> 5, lane = t & 31;
    for (int i = t; i < KDIM * 64; i += 256) Ws[i] = W[i];
    const float* base = xin ? xin : (const float*)g_feat;
    int row0 = blockIdx.x * 128;
    int r = w * 16;
    int rr = t & 127;
    int kq0 = (t >> 7) * 2;
    const float* xrow = base + (size_t)(row0 + rr) * instride + inoff;
    float2 acc[8][2];
#pragma unroll
    for (int i = 0; i < 8; i++) { acc[i][0] = make_float2(0.f, 0.f); acc[i][1] = acc[i][0]; }
    for (int kb = 0; kb < KDIM; kb += 16) {
        __syncthreads();
#pragma unroll
        for (int j = 0; j < 2; j++) {
            int kq = kq0 + j;
            float4 v = *(const float4*)&xrow[kb + kq * 4];
            xs[(kq * 4 + 0) * 128 + rr] = v.x;
            xs[(kq * 4 + 1) * 128 + rr] = v.y;
            xs[(kq * 4 + 2) * 128 + rr] = v.z;
            xs[(kq * 4 + 3) * 128 + rr] = v.w;
        }
        __syncthreads();
#pragma unroll
        for (int k = 0; k < 16; k++) {
            float2 wv = *(const float2*)&Ws[(kb + k) * 64 + lane * 2];
            float2 W0 = make_float2(wv.x, wv.x);
            float2 W1 = make_float2(wv.y, wv.y);
            const float4* xp = (const float4*)&xs[k * 128 + r];
            float4 xa = xp[0], xb = xp[1], xc = xp[2], xd = xp[3];
            float2 p;
            p = make_float2(xa.x, xa.y);
            acc[0][0] = ffma2(p, W0, acc[0][0]); acc[0][1] = ffma2(p, W1, acc[0][1]);
            p = make_float2(xa.z, xa.w);
            acc[1][0] = ffma2(p, W0, acc[1][0]); acc[1][1] = ffma2(p, W1, acc[1][1]);
            p = make_float2(xb.x, xb.y);
            acc[2][0] = ffma2(p, W0, acc[2][0]); acc[2][1] = ffma2(p, W1, acc[2][1]);
            p = make_float2(xb.z, xb.w);
            acc[3][0] = ffma2(p, W0, acc[3][0]); acc[3][1] = ffma2(p, W1, acc[3][1]);
            p = make_float2(xc.x, xc.y);
            acc[4][0] = ffma2(p, W0, acc[4][0]); acc[4][1] = ffma2(p, W1, acc[4][1]);
            p = make_float2(xc.z, xc.w);
            acc[5][0] = ffma2(p, W0, acc[5][0]); acc[5][1] = ffma2(p, W1, acc[5][1]);
            p = make_float2(xd.x, xd.y);
            acc[6][0] = ffma2(p, W0, acc[6][0]); acc[6][1] = ffma2(p, W1, acc[6][1]);
            p = make_float2(xd.z, xd.w);
            acc[7][0] = ffma2(p, W0, acc[7][0]); acc[7][1] = ffma2(p, W1, acc[7][1]);
        }
    }
#pragma unroll
    for (int i = 0; i < 8; i++) {
        size_t rb = (size_t)(row0 + r + 2 * i) * 64 + lane * 2;
        *(float2*)&g_h[rb]      = make_float2(acc[i][0].x, acc[i][1].x);
        *(float2*)&g_h[rb + 64] = make_float2(acc[i][0].y, acc[i][1].y);
    }
}

// ---------------- aggregation: TWO nodes per warp (16 lanes each) ----------
// Each half-warp owns a full node: 16 lanes x float4 = 64 cols.
// Edge guard moved to the (single) edge load; pad edges have coef=0.
// MLP=8 gathers in flight. Epilogue (bias+tanh+store+key) fully lane-utilized.
__global__ __launch_bounds__(256)
void k_agg(const float* __restrict__ bias, int outoff, int first) {
    int warp = blockIdx.x * 8 + (threadIdx.x >> 5);
    int lane = threadIdx.x & 31;
    int h = lane >> 4;                 // which node of the pair
    int l16 = lane & 15;
    int c4 = l16 * 4;                  // 4 cols per lane
    int n = warp * 2 + h;
    float di = g_dinv[n];
    float s = di * di;
    float4 hv = *(const float4*)&g_h[(size_t)n * 64 + c4];
    float2 acc0 = make_float2(hv.x * s, hv.y * s);
    float2 acc1 = make_float2(hv.z * s, hv.w * s);
    int beg = g_off[n] + g_bsum[n >> 10];
    int deg = g_cnt[n];
    int maxdeg = max(deg, __shfl_xor_sync(0xffffffffu, deg, 16));
    for (int bb = 0; bb < maxdeg; bb += 16) {
        int idx = bb + l16;
        int2 ed = (idx < deg) ? g_edge[beg + idx] : make_int2(n, 0);
        int se = ed.x;
        float ce = __int_as_float(ed.y);
#pragma unroll
        for (int i = 0; i < 16; i += 8) {
            int sj[8]; float cj[8];
#pragma unroll
            for (int j = 0; j < 8; j++) {
                int srcl = (h << 4) + i + j;     // broadcast from own half
                sj[j] = __shfl_sync(0xffffffffu, se, srcl);
                cj[j] = __shfl_sync(0xffffffffu, ce, srcl);
            }
            float4 v[8];
#pragma unroll
            for (int j = 0; j < 8; j++)
                v[j] = *(const float4*)&g_h[(size_t)sj[j] * 64 + c4];
#pragma unroll
            for (int j = 0; j < 8; j++) {
                float2 cc = make_float2(cj[j], cj[j]);
                acc0 = ffma2(make_float2(v[j].x, v[j].y), cc, acc0);
                acc1 = ffma2(make_float2(v[j].z, v[j].w), cc, acc1);
            }
        }
    }
    // epilogue — every lane active for its own node
    float4 bv = *(const float4*)&bias[c4];
    float t0 = fast_tanh(acc0.x + bv.x);
    float t1 = fast_tanh(acc0.y + bv.y);
    float t2 = fast_tanh(acc1.x + bv.z);
    float t3 = fast_tanh(acc1.y + bv.w);
    *(float4*)&g_feat[(size_t)n * 192 + outoff + c4] = make_float4(t0, t1, t2, t3);
    float m = fmaxf(fmaxf(t0, t1), fmaxf(t2, t3));
#pragma unroll
    for (int d = 8; d > 0; d >>= 1)    // reduce within the 16-lane half only
        m = fmaxf(m, __shfl_xor_sync(0xffffffffu, m, d));
    if (l16 == 0) g_key[n] = first ? m : fmaxf(g_key[n], m);
}

// ---------------- fused head: select + sort + conv1/pool/conv2/pool + FC ----
__global__ __launch_bounds__(320, 6)
void k_cnn(const float* __restrict__ Wc1, const float* __restrict__ bc1,
           const float* __restrict__ Wc2, const float* __restrict__ bc2,
           const float* __restrict__ Wf,  const float* __restrict__ bf,
           float* __restrict__ out_c, float* __restrict__ out_xf) {
    __shared__ float sp[10 * 192];   // sorted pooled tile (channel-major)
    __shared__ float s1[32 * 48];
    __shared__ float s2[32 * 12];
    __shared__ float s3[64 * 4];
    __shared__ float sxf[64];
    __shared__ float sk[64];
    __shared__ int   sel[16];
    int g = blockIdx.x, t = threadIdx.x;
    int w = t >> 5, lane = t & 31;

    if (t < NPG) {
        sk[t] = g_key[g * NPG + t];
        g_cnt[g * NPG + t] = 0;          // reset degree counters for next replay
    }
    __syncthreads();

    if (t < NPG) {
        float kv = sk[t];
        int r = 0;
        for (int j = 0; j < NPG; j++) {
            float kj = sk[j];
            r += (int)((kj > kv) || ((kj == kv) && (j < t)));
        }
        if (r < KTOP) sel[r] = g * NPG + t;
    }
    __syncthreads();

    // warps 0..9: sort own selected node's 192 feats ascending (bitonic-256)
    if (w < KTOP) {
        int node = sel[w];
        const float* f = g_feat + (size_t)node * 192;
        const float INF = __int_as_float(0x7f800000);
        float v[8];
#pragma unroll
        for (int r = 0; r < 8; r++) {
            int idx = r * 32 + lane;
            v[r] = (idx < 192) ? f[idx] : INF;
        }
#pragma unroll
        for (int k = 2; k <= 256; k <<= 1) {
#pragma unroll
            for (int j = 128; j > 0; j >>= 1) {
                if (j >= k) continue;
                if (j < 32) {
#pragma unroll
                    for (int r = 0; r < 8; r++) {
                        int idx = r * 32 + lane;
                        float o = __shfl_xor_sync(0xffffffffu, v[r], j);
                        bool up = ((idx & k) == 0);
                        bool lower = ((lane & j) == 0);
                        v[r] = (up == lower) ? fminf(v[r], o) : fmaxf(v[r], o);
                    }
                } else {
                    int jr = j >> 5;
#pragma unroll
                    for (int r = 0; r < 8; r++) {
                        if ((r & jr) == 0) {
                            int r2 = r | jr;
                            int idx = r * 32 + lane;
                            bool up = ((idx & k) == 0);
                            float a = v[r], b = v[r2];
                            v[r]  = up ? fminf(a, b) : fmaxf(a, b);
                            v[r2] = up ? fmaxf(a, b) : fminf(a, b);
                        }
                    }
                }
            }
        }
#pragma unroll
        for (int r = 0; r < 6; r++) sp[w * 192 + r * 32 + lane] = v[r];
    }
    __syncthreads();

    // conv1 (C_in=10, k=4, stride=4) + relu -> s1[32][48]
    if (w < 8) {
        const float4* sp4 = (const float4*)sp;
#pragma unroll
        for (int oo = 0; oo < 4; oo++) {
            int o = w * 4 + oo;
            const float4* w4 = (const float4*)&Wc1[o * 40];
            float a0 = bc1[o], a1 = a0;
#pragma unroll
            for (int i = 0; i < 10; i++) {
                float4 wv = w4[i];
                float4 xa = sp4[i * 48 + lane];
                a0 = fmaf(xa.x, wv.x, a0); a0 = fmaf(xa.y, wv.y, a0);
                a0 = fmaf(xa.z, wv.z, a0); a0 = fmaf(xa.w, wv.w, a0);
                if (lane < 16) {
                    float4 xb = sp4[i * 48 + 32 + lane];
                    a1 = fmaf(xb.x, wv.x, a1); a1 = fmaf(xb.y, wv.y, a1);
                    a1 = fmaf(xb.z, wv.z, a1); a1 = fmaf(xb.w, wv.w, a1);
                }
            }
            s1[o * 48 + lane] = fmaxf(a0, 0.f);
            if (lane < 16) s1[o * 48 + 32 + lane] = fmaxf(a1, 0.f);
        }
    }
    __syncthreads();

    // maxpool 4/4 -> s2[32][12]
    for (int idx = t; idx < 384; idx += 320) {
        int o = idx / 12, p = idx % 12;
        const float* r0 = &s1[o * 48 + p * 4];
        s2[idx] = fmaxf(fmaxf(r0[0], r0[1]), fmaxf(r0[2], r0[3]));
    }
    __syncthreads();

    // conv2 (C_in=32, k=3, stride=3) + relu -> s3[64][4]
    if (w < 8) {
        int p = lane & 3, ipart = lane >> 2;
#pragma unroll
        for (int j = 0; j < 8; j++) {
            int o = w * 8 + j;
            float acc = 0.f;
#pragma unroll
            for (int m = 0; m < 4; m++) {
                int i = ipart + m * 8;
                const float* s2r = &s2[i * 12 + p * 3];
                const float* w2r = &Wc2[o * 96 + i * 3];
                acc = fmaf(s2r[0], w2r[0], acc);
                acc = fmaf(s2r[1], w2r[1], acc);
                acc = fmaf(s2r[2], w2r[2], acc);
            }
            acc += __shfl_xor_sync(0xffffffffu, acc, 4);
            acc += __shfl_xor_sync(0xffffffffu, acc, 8);
            acc += __shfl_xor_sync(0xffffffffu, acc, 16);
            if (lane < 4) s3[o * 4 + p] = fmaxf(acc + bc2[o], 0.f);
        }
    }
    __syncthreads();

    // maxpool 4 -> xf[64]
    if (t < 64) {
        float m = fmaxf(fmaxf(s3[t * 4], s3[t * 4 + 1]),
                        fmaxf(s3[t * 4 + 2], s3[t * 4 + 3]));
        sxf[t] = m;
        out_xf[(size_t)g * 64 + t] = m;
    }
    __syncthreads();

    // FC: c = relu(xf) @ Wf + bf
    if (t < 10) {
        float acc = bf[t];
#pragma unroll
        for (int o = 0; o < 64; o++)
            acc = fmaf(fmaxf(sxf[o], 0.f), Wf[o * 10 + t], acc);
        out_c[(size_t)g * 10 + t] = acc;
    }
}

// ---------------- launcher ----------------
extern "C" void kernel_launch(void* const* d_in, const int* in_sizes, int n_in,
                              void* d_out, int out_size) {
    const float* x   = (const float*)d_in[0];
    const int*   ei  = (const int*)d_in[1];
    // d_in[2] = batch (implicit: repeat(arange(B), 50))
    const float* W1  = (const float*)d_in[3];
    const float* b1  = (const float*)d_in[4];
    const float* W2  = (const float*)d_in[5];
    const float* b2  = (const float*)d_in[6];
    const float* W3  = (const float*)d_in[7];
    const float* b3  = (const float*)d_in[8];
    const float* Wc1 = (const float*)d_in[9];
    const float* bc1 = (const float*)d_in[10];
    const float* Wc2 = (const float*)d_in[11];
    const float* bc2 = (const float*)d_in[12];
    const float* Wf  = (const float*)d_in[13];
    const float* bf  = (const float*)d_in[14];
    float* out = (float*)d_out;
    float* out_c  = out;                   // [B,10]
    float* out_xf = out + (size_t)BB * 10; // [B,64]

    const int4* row4 = (const int4*)ei;
    const int4* col4 = (const int4*)(ei + EE);

    // degree + CSR build (g_cnt zeroed by previous call's k_cnn; statics start 0)
    k_count<<<EE / 1024, 256>>>(col4);                 // 0
    k_scan_blk<<<200, 1024>>>();                       // 1 (+dinv +cursor)
    k_scan_top<<<1, 256>>>();                          // 2
    k_scatter<<<EE / 1024, 256>>>(row4, col4);         // 3
    // layer 1
    k_gemm<128><<<NN / 128, 256>>>(x, 128, 0, W1);     // 4
    k_agg<<<NN / 16, 256>>>(b1, 0, 1);                 // 5 <- ncu slot
    // layer 2
    k_gemm<64><<<NN / 128, 256>>>((const float*)0, 192, 0, W2);
    k_agg<<<NN / 16, 256>>>(b2, 64, 0);
    // layer 3
    k_gemm<64><<<NN / 128, 256>>>((const float*)0, 192, 64, W3);
    k_agg<<<NN / 16, 256>>>(b3, 128, 0);

    // fused select + sort + CNN head + FC (also resets g_cnt for next replay)
    k_cnn<<<BB, 320>>>(Wc1, bc1, Wc2, bc2, Wf, bf, out_c, out_xf);
}